// round 8
// baseline (speedup 1.0000x reference)
#include <cuda_runtime.h>

// 2-layer LSTM (H=30, IN=1) + linear head, B=512, T=2048.
// Block = 1 batch element, 128 threads = 4 warps, QUAD layout:
//   tid -> gate g = tid&3 (0=i,1=f,2=g,3=o), unit u = tid>>2 (30,31 pad).
// Weight rows (w_hh1, w_ih2, w_hh2) register-resident as f32x2 (90 regs).
// Iteration n: L1 step n + L2 step n-1 fused (both read h1[n-1], h2[n-2]);
// ONE __syncthreads per iteration; h/buffers ping-pong as compile-time
// pointers via a x2-unrolled steady loop (no parity arithmetic).
// FC head: pad lanes (tid 120-127, warp 3) compute out[n-2] POST-barrier at
// the start of iteration n, reading h2 from the read-buffer (ordered by the
// previous barrier; that buffer is not written this iteration).

#define Hs 30
#define Ts 2048
#define Bs 512

typedef unsigned long long ull;

__device__ __forceinline__ ull pk(float lo, float hi) {
    ull r; asm("mov.b64 %0, {%1, %2};" : "=l"(r) : "f"(lo), "f"(hi)); return r;
}
__device__ __forceinline__ void fma2(ull& d, ull a, ull b) {
    asm("fma.rn.f32x2 %0, %1, %2, %3;" : "=l"(d) : "l"(a), "l"(b), "l"(d));
}
__device__ __forceinline__ ull add2(ull a, ull b) {
    ull r; asm("add.rn.f32x2 %0, %1, %2;" : "=l"(r) : "l"(a), "l"(b)); return r;
}
__device__ __forceinline__ float hadd(ull a) {
    float lo, hi; asm("mov.b64 {%0, %1}, %2;" : "=f"(lo), "=f"(hi) : "l"(a)); return lo + hi;
}
__device__ __forceinline__ float ex2f(float x) { float y; asm("ex2.approx.f32 %0, %1;" : "=f"(y) : "f"(x)); return y; }
__device__ __forceinline__ float rcpf(float x) { float y; asm("rcp.approx.f32 %0, %1;" : "=f"(y) : "f"(x)); return y; }

__device__ __forceinline__ float act(float x, float aa, float bb, float cc) {
    return fmaf(aa, rcpf(1.0f + ex2f(bb * x)), cc);
}
__device__ __forceinline__ float tanh_(float x) {
    return fmaf(-2.0f, rcpf(ex2f(2.8853900817779268f * x) + 1.0f), 1.0f);
}

// Pad-lane FC: lanes 24-31 of warp 3 (tid 120-127) reduce w_fc . h2 from SMEM.
#define FC_EMIT(H2R, OUTP) { \
    if (tid >= 120) { \
        float4 h4 = *(const float4*)((H2R) + 4 * (tid - 120)); \
        float p = h4.x * wf.x + h4.y * wf.y + h4.z * wf.z + h4.w * wf.w; \
        p += __shfl_xor_sync(0xFF000000u, p, 4); \
        p += __shfl_xor_sync(0xFF000000u, p, 2); \
        p += __shfl_xor_sync(0xFF000000u, p, 1); \
        if (tid == 120) *(OUTP) = p + bfc; \
    } \
}

// One fused iteration. Reads H1R (h1[n-1]), H2R (h2[n-2]); writes H1W (h1[n]),
// H2W (h2[n-1]). Barrier at the end.
#define ITER(H1R, H2R, H1W, H2W, XV) { \
    const ulonglong2* hp1 = (const ulonglong2*)(H1R); \
    const ulonglong2* hp2 = (const ulonglong2*)(H2R); \
    ull a0 = 0ull, a1 = 0ull, e0 = 0ull, e1 = 0ull, d0 = 0ull, d1 = 0ull; \
    _Pragma("unroll") \
    for (int k = 0; k < 7; k++) { \
        ulonglong2 v1 = hp1[k]; \
        ulonglong2 v2 = hp2[k]; \
        fma2(a0, w1p[2 * k],     v1.x); \
        fma2(a1, w1p[2 * k + 1], v1.y); \
        fma2(e0, w2i[2 * k],     v1.x); \
        fma2(e1, w2i[2 * k + 1], v1.y); \
        fma2(d0, w2h[2 * k],     v2.x); \
        fma2(d1, w2h[2 * k + 1], v2.y); \
    } \
    { ull v1t = ((const ull*)(H1R))[14], v2t = ((const ull*)(H2R))[14]; \
      fma2(a0, w1p[14], v1t); \
      fma2(e0, w2i[14], v1t); \
      fma2(d0, w2h[14], v2t); } \
    float pre1 = fmaf((XV), k0, b1) + hadd(add2(a0, a1)); \
    float pre2 = b2 + hadd(add2(add2(e0, e1), add2(d0, d1))); \
    float av = act(pre1, aa, bb, cc); \
    float zv = act(pre2, aa, bb, cc); \
    { \
        float gi = __shfl_sync(0xffffffffu, av, base); \
        float gf = __shfl_sync(0xffffffffu, av, base + 1); \
        float gg = __shfl_sync(0xffffffffu, av, base + 2); \
        float go = __shfl_sync(0xffffffffu, av, base + 3); \
        c1 = fmaf(gf, c1, gi * gg); \
        if (g == 0) (H1W)[u] = go * tanh_(c1); \
    } \
    { \
        float qi = __shfl_sync(0xffffffffu, zv, base); \
        float qf = __shfl_sync(0xffffffffu, zv, base + 1); \
        float qg = __shfl_sync(0xffffffffu, zv, base + 2); \
        float qo = __shfl_sync(0xffffffffu, zv, base + 3); \
        c2 = fmaf(qf, c2, qi * qg); \
        if (g == 0) (H2W)[u] = qo * tanh_(c2); \
    } \
    __syncthreads(); \
}

__global__ void __launch_bounds__(128, 4) lstm_kernel(
    const float* __restrict__ x,
    const float* __restrict__ w_ih1, const float* __restrict__ w_hh1,
    const float* __restrict__ b_ih1, const float* __restrict__ b_hh1,
    const float* __restrict__ w_ih2, const float* __restrict__ w_hh2,
    const float* __restrict__ b_ih2, const float* __restrict__ b_hh2,
    const float* __restrict__ w_fc,  const float* __restrict__ b_fc,
    float* __restrict__ out)
{
    __shared__ __align__(16) float sx[Ts];
    __shared__ __align__(16) float h1A[32], h1B[32];
    __shared__ __align__(16) float h2A[32], h2B[32];

    const int tid  = threadIdx.x;
    const int g    = tid & 3;
    const int u    = tid >> 2;
    const int lane = tid & 31;
    const int base = lane & ~3;
    const int b    = blockIdx.x;

    {   // coalesced x preload
        const float4* xb4 = (const float4*)(x + (size_t)b * Ts);
        float4* sx4 = (float4*)sx;
        #pragma unroll
        for (int i = 0; i < Ts / 4 / 128; i++) sx4[tid + i * 128] = xb4[tid + i * 128];
    }
    if (tid < 32) {
        h1A[tid] = 0.0f; h1B[tid] = 0.0f;
        h2A[tid] = 0.0f; h2B[tid] = 0.0f;
    }

    // Register-resident weight rows for (gate g, unit u), f32x2 packed.
    const int row = g * Hs + ((u < Hs) ? u : Hs - 1);
    ull w1p[15], w2i[15], w2h[15];
    {
        const float* r1  = w_hh1 + row * Hs;
        const float* r2i = w_ih2 + row * Hs;
        const float* r2h = w_hh2 + row * Hs;
        #pragma unroll
        for (int k = 0; k < 15; k++) {
            w1p[k] = pk(r1[2 * k],  r1[2 * k + 1]);
            w2i[k] = pk(r2i[2 * k], r2i[2 * k + 1]);
            w2h[k] = pk(r2h[2 * k], r2h[2 * k + 1]);
        }
    }
    const float k0 = w_ih1[row];
    const float b1 = b_ih1[row] + b_hh1[row];
    const float b2 = b_ih2[row] + b_hh2[row];
    const float bfc = b_fc[0];

    // Pad-lane FC weights (tid 120-127 -> j = tid-120, covers units 4j..4j+3;
    // entries 30,31 zeroed).
    float4 wf;
    {
        int j = (tid >= 120) ? (tid - 120) : 0;
        wf.x = (4 * j + 0 < Hs) ? w_fc[4 * j + 0] : 0.0f;
        wf.y = (4 * j + 1 < Hs) ? w_fc[4 * j + 1] : 0.0f;
        wf.z = (4 * j + 2 < Hs) ? w_fc[4 * j + 2] : 0.0f;
        wf.w = (4 * j + 3 < Hs) ? w_fc[4 * j + 3] : 0.0f;
    }

    const float aa = (g == 2) ? 2.0f : 1.0f;
    const float bb = (g == 2) ? -2.8853900817779268f : -1.4426950408889634f;
    const float cc = (g == 2) ? -1.0f : 0.0f;

    float c1 = 0.0f, c2 = 0.0f;
    float* __restrict__ outb = out + (size_t)b * Ts;

    __syncthreads();

    // ---- Prologue n = 0: L1 step 0 only (h1[-1] = 0) -> h1B ----
    {
        float a = act(fmaf(sx[0], k0, b1), aa, bb, cc);
        float gi = __shfl_sync(0xffffffffu, a, base);
        float gg = __shfl_sync(0xffffffffu, a, base + 2);
        float go = __shfl_sync(0xffffffffu, a, base + 3);
        c1 = gi * gg;
        if (g == 0) h1B[u] = go * tanh_(c1);
        __syncthreads();
    }

    // ---- n = 1: read B (h1[0], h2[-1]=0), write A; no FC emit yet ----
    ITER(h1B, h2B, h1A, h2A, sx[1]);

    // ---- Steady pairs: n = 2k, 2k+1 for k = 1..1023 ----
    const float* sxp = sx + 2;
    float* op = outb;            // op[0] = out[n-2] for the even step
    #pragma unroll 1
    for (int k = 1; k <= (Ts - 2) / 2; k++) {
        // n even: read A (h1[n-1], h2[n-2]), write B; FC emits out[n-2] from h2A
        FC_EMIT(h2A, op);
        ITER(h1A, h2A, h1B, h2B, sxp[0]);
        // n odd: read B, write A; FC emits out[n-1] from h2B
        FC_EMIT(h2B, op + 1);
        ITER(h1B, h2B, h1A, h2A, sxp[1]);
        sxp += 2;
        op  += 2;
    }
    // After loop: h1A = h1[2047], h2A = h2[2046]; emitted out[0..2045].

    // ---- Epilogue E1: FC out[2046] from h2A; L2 step 2047 -> h2B ----
    FC_EMIT(h2A, outb + Ts - 2);
    {
        const ulonglong2* hp1 = (const ulonglong2*)h1A;
        const ulonglong2* hp2 = (const ulonglong2*)h2A;
        ull e0 = 0ull, e1 = 0ull, d0 = 0ull, d1 = 0ull;
        #pragma unroll
        for (int k = 0; k < 7; k++) {
            ulonglong2 v1 = hp1[k];
            ulonglong2 v2 = hp2[k];
            fma2(e0, w2i[2 * k],     v1.x);
            fma2(e1, w2i[2 * k + 1], v1.y);
            fma2(d0, w2h[2 * k],     v2.x);
            fma2(d1, w2h[2 * k + 1], v2.y);
        }
        fma2(e0, w2i[14], ((const ull*)h1A)[14]);
        fma2(d0, w2h[14], ((const ull*)h2A)[14]);
        float zv = act(b2 + hadd(add2(add2(e0, e1), add2(d0, d1))), aa, bb, cc);
        float qi = __shfl_sync(0xffffffffu, zv, base);
        float qf = __shfl_sync(0xffffffffu, zv, base + 1);
        float qg = __shfl_sync(0xffffffffu, zv, base + 2);
        float qo = __shfl_sync(0xffffffffu, zv, base + 3);
        c2 = fmaf(qf, c2, qi * qg);
        if (g == 0) h2B[u] = qo * tanh_(c2);
        __syncthreads();
    }
    // ---- Epilogue E2: FC out[2047] from h2B ----
    FC_EMIT(h2B, outb + Ts - 1);
}

extern "C" void kernel_launch(void* const* d_in, const int* in_sizes, int n_in,
                              void* d_out, int out_size) {
    (void)in_sizes; (void)n_in; (void)out_size;
    lstm_kernel<<<Bs, 128>>>(
        (const float*)d_in[0],
        (const float*)d_in[1], (const float*)d_in[2],
        (const float*)d_in[3], (const float*)d_in[4],
        (const float*)d_in[5], (const float*)d_in[6],
        (const float*)d_in[7], (const float*)d_in[8],
        (const float*)d_in[9], (const float*)d_in[10],
        (float*)d_out);
}

// round 9
// speedup vs baseline: 1.1482x; 1.1482x over previous
#include <cuda_runtime.h>

// 2-layer LSTM (H=30, IN=1) + linear head, B=512, T=2048.
// R7 skeleton (best: 1350us): block = 1 element, 128 thr = 4 warps, QUAD
// layout (tid -> gate g=tid&3, unit u=tid>>2; 30,31 pad). Weight rows
// register-resident f32x2 (90 regs). Iter n: L1 step n + L2 step n-1 fused,
// ONE __syncthreads/iter. FC: per-warp tail butterfly -> sp partials; tid127
// emits out[n-2] at the head of iter n (R7 placement, R8's warp-3 head
// butterfly regressed).
// This round: (a) steady loop unrolled x2 with compile-time ping-pong buffers
// (no parity ALU, validated R5); (b) FC butterfly 5 -> 3 shfl (nonzero
// contributions only on quad-base lanes, stride 4: xor 4,8,16 suffices).

#define Hs 30
#define Ts 2048
#define Bs 512

typedef unsigned long long ull;

__device__ __forceinline__ ull pk(float lo, float hi) {
    ull r; asm("mov.b64 %0, {%1, %2};" : "=l"(r) : "f"(lo), "f"(hi)); return r;
}
__device__ __forceinline__ void fma2(ull& d, ull a, ull b) {
    asm("fma.rn.f32x2 %0, %1, %2, %3;" : "=l"(d) : "l"(a), "l"(b), "l"(d));
}
__device__ __forceinline__ ull add2(ull a, ull b) {
    ull r; asm("add.rn.f32x2 %0, %1, %2;" : "=l"(r) : "l"(a), "l"(b)); return r;
}
__device__ __forceinline__ float hadd(ull a) {
    float lo, hi; asm("mov.b64 {%0, %1}, %2;" : "=f"(lo), "=f"(hi) : "l"(a)); return lo + hi;
}
__device__ __forceinline__ float ex2f(float x) { float y; asm("ex2.approx.f32 %0, %1;" : "=f"(y) : "f"(x)); return y; }
__device__ __forceinline__ float rcpf(float x) { float y; asm("rcp.approx.f32 %0, %1;" : "=f"(y) : "f"(x)); return y; }

__device__ __forceinline__ float act(float x, float aa, float bb, float cc) {
    return fmaf(aa, rcpf(1.0f + ex2f(bb * x)), cc);
}
__device__ __forceinline__ float tanh_(float x) {
    return fmaf(-2.0f, rcpf(ex2f(2.8853900817779268f * x) + 1.0f), 1.0f);
}

// One fused iteration. Reads H1R=h1[n-1], H2R=h2[n-2]; writes H1W=h1[n],
// H2W=h2[n-1]; FC partial of h2[n-1] -> SPW. tid127 first emits out[n-2]
// from SPR (written last iteration; ordered by last iteration's barrier).
#define ITER(H1R, H2R, H1W, H2W, SPR, SPW, XV, OUTP, DO_EMIT) { \
    if (DO_EMIT) { \
        if (tid == 127) { \
            float4 s4 = *(const float4*)(SPR); \
            *(OUTP) = s4.x + s4.y + s4.z + s4.w + bfc; \
        } \
    } \
    const ulonglong2* hp1 = (const ulonglong2*)(H1R); \
    const ulonglong2* hp2 = (const ulonglong2*)(H2R); \
    ull a0 = 0ull, a1 = 0ull, e0 = 0ull, e1 = 0ull, d0 = 0ull, d1 = 0ull; \
    _Pragma("unroll") \
    for (int k = 0; k < 7; k++) { \
        ulonglong2 v1 = hp1[k]; \
        ulonglong2 v2 = hp2[k]; \
        fma2(a0, w1p[2 * k],     v1.x); \
        fma2(a1, w1p[2 * k + 1], v1.y); \
        fma2(e0, w2i[2 * k],     v1.x); \
        fma2(e1, w2i[2 * k + 1], v1.y); \
        fma2(d0, w2h[2 * k],     v2.x); \
        fma2(d1, w2h[2 * k + 1], v2.y); \
    } \
    { ull v1t = ((const ull*)(H1R))[14], v2t = ((const ull*)(H2R))[14]; \
      fma2(a0, w1p[14], v1t); \
      fma2(e0, w2i[14], v1t); \
      fma2(d0, w2h[14], v2t); } \
    float pre1 = fmaf((XV), k0, b1) + hadd(add2(a0, a1)); \
    float pre2 = b2 + hadd(add2(add2(e0, e1), add2(d0, d1))); \
    float av = act(pre1, aa, bb, cc); \
    float zv = act(pre2, aa, bb, cc); \
    { \
        float gi = __shfl_sync(0xffffffffu, av, base); \
        float gf = __shfl_sync(0xffffffffu, av, base + 1); \
        float gg = __shfl_sync(0xffffffffu, av, base + 2); \
        float go = __shfl_sync(0xffffffffu, av, base + 3); \
        c1 = fmaf(gf, c1, gi * gg); \
        if (g == 0) (H1W)[u] = go * tanh_(c1); \
    } \
    { \
        float qi = __shfl_sync(0xffffffffu, zv, base); \
        float qf = __shfl_sync(0xffffffffu, zv, base + 1); \
        float qg = __shfl_sync(0xffffffffu, zv, base + 2); \
        float qo = __shfl_sync(0xffffffffu, zv, base + 3); \
        c2 = fmaf(qf, c2, qi * qg); \
        float h2v = qo * tanh_(c2); \
        if (g == 0) (H2W)[u] = h2v; \
        float p = wfc * h2v; \
        p += __shfl_xor_sync(0xffffffffu, p, 4); \
        p += __shfl_xor_sync(0xffffffffu, p, 8); \
        p += __shfl_xor_sync(0xffffffffu, p, 16); \
        if (lane == 0) (SPW)[wid] = p; \
    } \
    __syncthreads(); \
}

__global__ void __launch_bounds__(128, 4) lstm_kernel(
    const float* __restrict__ x,
    const float* __restrict__ w_ih1, const float* __restrict__ w_hh1,
    const float* __restrict__ b_ih1, const float* __restrict__ b_hh1,
    const float* __restrict__ w_ih2, const float* __restrict__ w_hh2,
    const float* __restrict__ b_ih2, const float* __restrict__ b_hh2,
    const float* __restrict__ w_fc,  const float* __restrict__ b_fc,
    float* __restrict__ out)
{
    __shared__ __align__(16) float sx[Ts];
    __shared__ __align__(16) float h1A[32], h1B[32];
    __shared__ __align__(16) float h2A[32], h2B[32];
    __shared__ __align__(16) float spA[4], spB[4];

    const int tid  = threadIdx.x;
    const int g    = tid & 3;
    const int u    = tid >> 2;
    const int lane = tid & 31;
    const int wid  = tid >> 5;
    const int base = lane & ~3;
    const int b    = blockIdx.x;

    {   // coalesced x preload
        const float4* xb4 = (const float4*)(x + (size_t)b * Ts);
        float4* sx4 = (float4*)sx;
        #pragma unroll
        for (int i = 0; i < Ts / 4 / 128; i++) sx4[tid + i * 128] = xb4[tid + i * 128];
    }
    if (tid < 32) {
        h1A[tid] = 0.0f; h1B[tid] = 0.0f;
        h2A[tid] = 0.0f; h2B[tid] = 0.0f;
    }

    // Register-resident weight rows for (gate g, unit u), f32x2 packed.
    const int row = g * Hs + ((u < Hs) ? u : Hs - 1);
    ull w1p[15], w2i[15], w2h[15];
    {
        const float* r1  = w_hh1 + row * Hs;
        const float* r2i = w_ih2 + row * Hs;
        const float* r2h = w_hh2 + row * Hs;
        #pragma unroll
        for (int k = 0; k < 15; k++) {
            w1p[k] = pk(r1[2 * k],  r1[2 * k + 1]);
            w2i[k] = pk(r2i[2 * k], r2i[2 * k + 1]);
            w2h[k] = pk(r2h[2 * k], r2h[2 * k + 1]);
        }
    }
    const float k0  = w_ih1[row];
    const float b1  = b_ih1[row] + b_hh1[row];
    const float b2  = b_ih2[row] + b_hh2[row];
    const float wfc = (g == 0 && u < Hs) ? w_fc[u] : 0.0f;
    const float bfc = b_fc[0];

    const float aa = (g == 2) ? 2.0f : 1.0f;
    const float bb = (g == 2) ? -2.8853900817779268f : -1.4426950408889634f;
    const float cc = (g == 2) ? -1.0f : 0.0f;

    float c1 = 0.0f, c2 = 0.0f;
    float* __restrict__ outb = out + (size_t)b * Ts;

    __syncthreads();

    // ---- Prologue n = 0: L1 step 0 only (h1[-1]=0) -> h1B ----
    {
        float a = act(fmaf(sx[0], k0, b1), aa, bb, cc);
        float gi = __shfl_sync(0xffffffffu, a, base);
        float gg = __shfl_sync(0xffffffffu, a, base + 2);
        float go = __shfl_sync(0xffffffffu, a, base + 3);
        c1 = gi * gg;
        if (g == 0) h1B[u] = go * tanh_(c1);
        __syncthreads();
    }

    // ---- n = 1 (odd): read B, write A, partial->spA; no emit ----
    ITER(h1B, h2B, h1A, h2A, spB, spA, sx[1], outb, false);

    // ---- Steady pairs: n = 2+2k (even: read A write B, emit spA),
    //                    n = 3+2k (odd:  read B write A, emit spB) ----
    const float* sxp = sx + 2;
    float* op = outb;    // op[0] = out at (even n) - 2
    #pragma unroll 1
    for (int k2 = 0; k2 < (Ts - 2) / 2; k2++) {
        ITER(h1A, h2A, h1B, h2B, spA, spB, sxp[0], op, true);
        ITER(h1B, h2B, h1A, h2A, spB, spA, sxp[1], op + 1, true);
        sxp += 2;
        op  += 2;
    }
    // After loop: last iter n=2047 (odd) wrote A (h1[2047], h2[2046]), spA.

    // ---- Epilogue: emit out[2046] from spA; L2-only step 2047 -> spB ----
    if (tid == 127) {
        float4 s4 = *(const float4*)spA;
        outb[Ts - 2] = s4.x + s4.y + s4.z + s4.w + bfc;
    }
    {
        const ulonglong2* hp1 = (const ulonglong2*)h1A;
        const ulonglong2* hp2 = (const ulonglong2*)h2A;
        ull e0 = 0ull, e1 = 0ull, d0 = 0ull, d1 = 0ull;
        #pragma unroll
        for (int k = 0; k < 7; k++) {
            ulonglong2 v1 = hp1[k];
            ulonglong2 v2 = hp2[k];
            fma2(e0, w2i[2 * k],     v1.x);
            fma2(e1, w2i[2 * k + 1], v1.y);
            fma2(d0, w2h[2 * k],     v2.x);
            fma2(d1, w2h[2 * k + 1], v2.y);
        }
        fma2(e0, w2i[14], ((const ull*)h1A)[14]);
        fma2(d0, w2h[14], ((const ull*)h2A)[14]);
        float zv = act(b2 + hadd(add2(add2(e0, e1), add2(d0, d1))), aa, bb, cc);
        float qi = __shfl_sync(0xffffffffu, zv, base);
        float qf = __shfl_sync(0xffffffffu, zv, base + 1);
        float qg = __shfl_sync(0xffffffffu, zv, base + 2);
        float qo = __shfl_sync(0xffffffffu, zv, base + 3);
        c2 = fmaf(qf, c2, qi * qg);
        float h2v = qo * tanh_(c2);
        float p = wfc * h2v;
        p += __shfl_xor_sync(0xffffffffu, p, 4);
        p += __shfl_xor_sync(0xffffffffu, p, 8);
        p += __shfl_xor_sync(0xffffffffu, p, 16);
        if (lane == 0) spB[wid] = p;
        __syncthreads();
    }
    if (tid == 127) {
        float4 s4 = *(const float4*)spB;
        outb[Ts - 1] = s4.x + s4.y + s4.z + s4.w + bfc;
    }
}

extern "C" void kernel_launch(void* const* d_in, const int* in_sizes, int n_in,
                              void* d_out, int out_size) {
    (void)in_sizes; (void)n_in; (void)out_size;
    lstm_kernel<<<Bs, 128>>>(
        (const float*)d_in[0],
        (const float*)d_in[1], (const float*)d_in[2],
        (const float*)d_in[3], (const float*)d_in[4],
        (const float*)d_in[5], (const float*)d_in[6],
        (const float*)d_in[7], (const float*)d_in[8],
        (const float*)d_in[9], (const float*)d_in[10],
        (float*)d_out);
}

// round 10
// speedup vs baseline: 1.3305x; 1.1588x over previous
#include <cuda_runtime.h>

// 2-layer LSTM (H=30, IN=1) + linear head, B=512, T=2048.
// R9 skeleton: block = 1 element, 128 thr = 4 warps, QUAD layout
// (g = tid&3: 0=i,1=f,2=g,3=o; u = tid>>2; units 30,31 pad). Weight rows
// register-resident f32x2. Iter n: L1 step n + L2 step n-1 fused, ONE
// __syncthreads/iter, ping-pong buffers via x2-unrolled steady loop.
// This round (chain-only attack):
//  (a) FC head folded into lane 127's otherwise-wasted d-dot: its w2h regs
//      hold w_fc, so hadd(d) = out[n-2] directly. The per-warp FC butterfly
//      tail (3 shfl + STS) and sp buffers are DELETED.
//  (b) weights/biases pre-scaled by -log2e (sigmoid) / -2log2e (tanh gate):
//      act(pre) needs no leading multiply.
//  (c) cell state kept scaled: c' = 2*log2e*c (g-gate lane emits scaled
//      tanh via adjusted aa/cc), so tanh(c) needs no leading multiply.

#define Hs 30
#define Ts 2048
#define Bs 512

#define L2E  1.4426950408889634f
#define K2E  2.8853900817779268f   // 2*log2e
#define AA_G 5.7707801635558536f   // 2*K2E
#define CC_G (-2.8853900817779268f)

typedef unsigned long long ull;

__device__ __forceinline__ ull pk(float lo, float hi) {
    ull r; asm("mov.b64 %0, {%1, %2};" : "=l"(r) : "f"(lo), "f"(hi)); return r;
}
__device__ __forceinline__ void fma2(ull& d, ull a, ull b) {
    asm("fma.rn.f32x2 %0, %1, %2, %3;" : "=l"(d) : "l"(a), "l"(b), "l"(d));
}
__device__ __forceinline__ ull add2(ull a, ull b) {
    ull r; asm("add.rn.f32x2 %0, %1, %2;" : "=l"(r) : "l"(a), "l"(b)); return r;
}
__device__ __forceinline__ float hadd(ull a) {
    float lo, hi; asm("mov.b64 {%0, %1}, %2;" : "=f"(lo), "=f"(hi) : "l"(a)); return lo + hi;
}
__device__ __forceinline__ float ex2f(float x) { float y; asm("ex2.approx.f32 %0, %1;" : "=f"(y) : "f"(x)); return y; }
__device__ __forceinline__ float rcpf(float x) { float y; asm("rcp.approx.f32 %0, %1;" : "=f"(y) : "f"(x)); return y; }

// act on PRE-SCALED input p (already multiplied by -log2e or -2log2e):
//   sigmoid lane: aa=1, cc=0  -> rcp(1+ex2(p))
//   tanh-gate lane (scaled output K2E*tanh): aa=2*K2E, cc=-K2E
__device__ __forceinline__ float act(float p, float aa, float cc) {
    return fmaf(aa, rcpf(1.0f + ex2f(p)), cc);
}
// tanh(c) from SCALED state c' = K2E*c:  1 - 2*rcp(1+ex2(c'))
__device__ __forceinline__ float tanhs(float cp) {
    return fmaf(-2.0f, rcpf(1.0f + ex2f(cp)), 1.0f);
}

// One fused iteration. Reads H1R=h1[n-1], H2R=h2[n-2]; writes H1W=h1[n],
// H2W=h2[n-1]. Lane 127's d-dot IS the FC dot: emits out[n-2] mid-iter.
#define ITER(H1R, H2R, H1W, H2W, XV, OUTP, DO_EMIT) { \
    const ulonglong2* hp1 = (const ulonglong2*)(H1R); \
    const ulonglong2* hp2 = (const ulonglong2*)(H2R); \
    ull a0 = 0ull, a1 = 0ull, e0 = 0ull, e1 = 0ull, d0 = 0ull, d1 = 0ull; \
    _Pragma("unroll") \
    for (int k = 0; k < 7; k++) { \
        ulonglong2 v1 = hp1[k]; \
        ulonglong2 v2 = hp2[k]; \
        fma2(a0, w1p[2 * k],     v1.x); \
        fma2(a1, w1p[2 * k + 1], v1.y); \
        fma2(e0, w2i[2 * k],     v1.x); \
        fma2(e1, w2i[2 * k + 1], v1.y); \
        fma2(d0, w2h[2 * k],     v2.x); \
        fma2(d1, w2h[2 * k + 1], v2.y); \
    } \
    { ull v1t = ((const ull*)(H1R))[14], v2t = ((const ull*)(H2R))[14]; \
      fma2(a0, w1p[14], v1t); \
      fma2(e0, w2i[14], v1t); \
      fma2(d0, w2h[14], v2t); } \
    float hd = hadd(add2(d0, d1)); \
    if (DO_EMIT) { if (tid == 127) *(OUTP) = hd + bfc; } \
    float pre1 = fmaf((XV), k0, b1) + hadd(add2(a0, a1)); \
    float pre2 = (b2 + hadd(add2(e0, e1))) + hd; \
    float av = act(pre1, aa, cc); \
    float zv = act(pre2, aa, cc); \
    { \
        float gi = __shfl_sync(0xffffffffu, av, base); \
        float gf = __shfl_sync(0xffffffffu, av, base + 1); \
        float gg = __shfl_sync(0xffffffffu, av, base + 2); \
        float go = __shfl_sync(0xffffffffu, av, base + 3); \
        c1 = fmaf(gf, c1, gi * gg); \
        if (g == 0) (H1W)[u] = go * tanhs(c1); \
    } \
    { \
        float qi = __shfl_sync(0xffffffffu, zv, base); \
        float qf = __shfl_sync(0xffffffffu, zv, base + 1); \
        float qg = __shfl_sync(0xffffffffu, zv, base + 2); \
        float qo = __shfl_sync(0xffffffffu, zv, base + 3); \
        c2 = fmaf(qf, c2, qi * qg); \
        if (g == 0) (H2W)[u] = qo * tanhs(c2); \
    } \
    __syncthreads(); \
}

__global__ void __launch_bounds__(128, 4) lstm_kernel(
    const float* __restrict__ x,
    const float* __restrict__ w_ih1, const float* __restrict__ w_hh1,
    const float* __restrict__ b_ih1, const float* __restrict__ b_hh1,
    const float* __restrict__ w_ih2, const float* __restrict__ w_hh2,
    const float* __restrict__ b_ih2, const float* __restrict__ b_hh2,
    const float* __restrict__ w_fc,  const float* __restrict__ b_fc,
    float* __restrict__ out)
{
    __shared__ __align__(16) float sx[Ts];
    __shared__ __align__(16) float h1A[32], h1B[32];
    __shared__ __align__(16) float h2A[32], h2B[32];

    const int tid  = threadIdx.x;
    const int g    = tid & 3;
    const int u    = tid >> 2;
    const int lane = tid & 31;
    const int base = lane & ~3;
    const int b    = blockIdx.x;

    {   // coalesced x preload
        const float4* xb4 = (const float4*)(x + (size_t)b * Ts);
        float4* sx4 = (float4*)sx;
        #pragma unroll
        for (int i = 0; i < Ts / 4 / 128; i++) sx4[tid + i * 128] = xb4[tid + i * 128];
    }
    if (tid < 32) {
        h1A[tid] = 0.0f; h1B[tid] = 0.0f;
        h2A[tid] = 0.0f; h2B[tid] = 0.0f;
    }

    // Per-lane input scale: sigmoid lanes -log2e, tanh-gate lanes -2log2e.
    const float s = (g == 2) ? -K2E : -L2E;
    const bool  fc_lane = (tid == 127);

    // Register-resident weight rows, PRE-SCALED by s. Lane 127's w2h slot
    // holds w_fc UNSCALED (its d-dot becomes the FC dot).
    const int row = g * Hs + ((u < Hs) ? u : Hs - 1);
    ull w1p[15], w2i[15], w2h[15];
    {
        const float* r1  = w_hh1 + row * Hs;
        const float* r2i = w_ih2 + row * Hs;
        const float* r2h = fc_lane ? w_fc : (w_hh2 + row * Hs);
        const float  s2h = fc_lane ? 1.0f : s;
        #pragma unroll
        for (int k = 0; k < 15; k++) {
            w1p[k] = pk(s * r1[2 * k],    s * r1[2 * k + 1]);
            w2i[k] = pk(s * r2i[2 * k],   s * r2i[2 * k + 1]);
            w2h[k] = pk(s2h * r2h[2 * k], s2h * r2h[2 * k + 1]);
        }
    }
    const float k0  = s * w_ih1[row];
    const float b1  = s * (b_ih1[row] + b_hh1[row]);
    const float b2  = s * (b_ih2[row] + b_hh2[row]);
    const float bfc = b_fc[0];

    // Activation output constants: tanh-gate lane emits K2E*tanh (scaled for
    // the c' recurrence); sigmoid lanes emit plain sigmoid.
    const float aa = (g == 2) ? AA_G : 1.0f;
    const float cc = (g == 2) ? CC_G : 0.0f;

    float c1 = 0.0f, c2 = 0.0f;   // SCALED cell states (c' = K2E * c)
    float* __restrict__ outb = out + (size_t)b * Ts;

    __syncthreads();

    // ---- Prologue n = 0: L1 step 0 only (h1[-1]=0) -> h1B ----
    {
        float a = act(fmaf(sx[0], k0, b1), aa, cc);
        float gi = __shfl_sync(0xffffffffu, a, base);
        float gg = __shfl_sync(0xffffffffu, a, base + 2);
        float go = __shfl_sync(0xffffffffu, a, base + 3);
        c1 = gi * gg;
        if (g == 0) h1B[u] = go * tanhs(c1);
        __syncthreads();
    }

    // ---- n = 1: read B (h2[-1]=0), write A; no emit ----
    ITER(h1B, h2B, h1A, h2A, sx[1], outb, false);

    // ---- Steady pairs: n = 2+2k (A->B), n = 3+2k (B->A), k = 0..1022 ----
    const float* sxp = sx + 2;
    float* op = outb;   // op[0] = out[n-2] at even n
    #pragma unroll 1
    for (int k2 = 0; k2 < (Ts - 2) / 2; k2++) {
        ITER(h1A, h2A, h1B, h2B, sxp[0], op,     true);
        ITER(h1B, h2B, h1A, h2A, sxp[1], op + 1, true);
        sxp += 2;
        op  += 2;
    }
    // After loop: h1A = h1[2047], h2A = h2[2046]; emitted out[0..2045].

    // ---- Epilogue: L2-only step 2047; lane127's d-dot emits out[2046] ----
    {
        const ulonglong2* hp1 = (const ulonglong2*)h1A;
        const ulonglong2* hp2 = (const ulonglong2*)h2A;
        ull e0 = 0ull, e1 = 0ull, d0 = 0ull, d1 = 0ull;
        #pragma unroll
        for (int k = 0; k < 7; k++) {
            ulonglong2 v1 = hp1[k];
            ulonglong2 v2 = hp2[k];
            fma2(e0, w2i[2 * k],     v1.x);
            fma2(e1, w2i[2 * k + 1], v1.y);
            fma2(d0, w2h[2 * k],     v2.x);
            fma2(d1, w2h[2 * k + 1], v2.y);
        }
        fma2(e0, w2i[14], ((const ull*)h1A)[14]);
        fma2(d0, w2h[14], ((const ull*)h2A)[14]);
        float hd = hadd(add2(d0, d1));
        if (tid == 127) outb[Ts - 2] = hd + bfc;
        float pre2 = (b2 + hadd(add2(e0, e1))) + hd;
        float zv = act(pre2, aa, cc);
        float qi = __shfl_sync(0xffffffffu, zv, base);
        float qf = __shfl_sync(0xffffffffu, zv, base + 1);
        float qg = __shfl_sync(0xffffffffu, zv, base + 2);
        float qo = __shfl_sync(0xffffffffu, zv, base + 3);
        c2 = fmaf(qf, c2, qi * qg);
        if (g == 0) h2B[u] = qo * tanhs(c2);
        __syncthreads();
    }
    // ---- Final: out[2047] = w_fc . h2[2047] (lane 127 mini-dot) ----
    if (tid == 127) {
        const ulonglong2* hp2 = (const ulonglong2*)h2B;
        ull d0 = 0ull, d1 = 0ull;
        #pragma unroll
        for (int k = 0; k < 7; k++) {
            ulonglong2 v2 = hp2[k];
            fma2(d0, w2h[2 * k],     v2.x);
            fma2(d1, w2h[2 * k + 1], v2.y);
        }
        fma2(d0, w2h[14], ((const ull*)h2B)[14]);
        outb[Ts - 1] = hadd(add2(d0, d1)) + bfc;
    }
}

extern "C" void kernel_launch(void* const* d_in, const int* in_sizes, int n_in,
                              void* d_out, int out_size) {
    (void)in_sizes; (void)n_in; (void)out_size;
    lstm_kernel<<<Bs, 128>>>(
        (const float*)d_in[0],
        (const float*)d_in[1], (const float*)d_in[2],
        (const float*)d_in[3], (const float*)d_in[4],
        (const float*)d_in[5], (const float*)d_in[6],
        (const float*)d_in[7], (const float*)d_in[8],
        (const float*)d_in[9], (const float*)d_in[10],
        (float*)d_out);
}

// round 11
// speedup vs baseline: 1.4341x; 1.0778x over previous
#include <cuda_runtime.h>

// 2-layer LSTM (H=30, IN=1) + linear head, B=512, T=2048.
// Skeleton (R10, 1170us): block = 1 element, 128 thr = 4 warps, QUAD layout
// (g = tid&3: 0=i,1=f,2=g,3=o; u = tid>>2; units 30,31 pad). Weight rows
// register-resident f32x2, PRE-SCALED by -log2e / -2log2e; cell state kept
// scaled (c' = 2log2e*c). Iter n: L1 step n + L2 step n-1 fused, ONE
// __syncthreads/iter, ping-pong buffers, x-unrolled steady loop.
// This round:
//  (a) FC fold stage 2: lane 127 has w2i=0, b2=0, w2h=w_fc, so its merged
//      pre2 IS w_fc.h2[n-2]; pre2 now uses ONE hadd for all lanes and the
//      separate hd path is gone.
//  (b) SHFL 8->6: o-gate lane (g==3) keeps o locally, computes and writes h.
//  (c) steady loop unrolled x4 (two ping-pong pairs per body).

#define Hs 30
#define Ts 2048
#define Bs 512

#define L2E  1.4426950408889634f
#define K2E  2.8853900817779268f   // 2*log2e
#define AA_G 5.7707801635558536f   // 2*K2E
#define CC_G (-2.8853900817779268f)

typedef unsigned long long ull;

__device__ __forceinline__ ull pk(float lo, float hi) {
    ull r; asm("mov.b64 %0, {%1, %2};" : "=l"(r) : "f"(lo), "f"(hi)); return r;
}
__device__ __forceinline__ void fma2(ull& d, ull a, ull b) {
    asm("fma.rn.f32x2 %0, %1, %2, %3;" : "=l"(d) : "l"(a), "l"(b), "l"(d));
}
__device__ __forceinline__ ull add2(ull a, ull b) {
    ull r; asm("add.rn.f32x2 %0, %1, %2;" : "=l"(r) : "l"(a), "l"(b)); return r;
}
__device__ __forceinline__ float hadd(ull a) {
    float lo, hi; asm("mov.b64 {%0, %1}, %2;" : "=f"(lo), "=f"(hi) : "l"(a)); return lo + hi;
}
__device__ __forceinline__ float ex2f(float x) { float y; asm("ex2.approx.f32 %0, %1;" : "=f"(y) : "f"(x)); return y; }
__device__ __forceinline__ float rcpf(float x) { float y; asm("rcp.approx.f32 %0, %1;" : "=f"(y) : "f"(x)); return y; }

// act on PRE-SCALED input p: sigmoid lanes aa=1,cc=0; tanh-gate lane emits
// K2E*tanh via aa=2*K2E, cc=-K2E.
__device__ __forceinline__ float act(float p, float aa, float cc) {
    return fmaf(aa, rcpf(1.0f + ex2f(p)), cc);
}
// tanh(c) from SCALED state c' = K2E*c
__device__ __forceinline__ float tanhs(float cp) {
    return fmaf(-2.0f, rcpf(1.0f + ex2f(cp)), 1.0f);
}

// One fused iteration. Reads H1R=h1[n-1], H2R=h2[n-2]; writes H1W=h1[n],
// H2W=h2[n-1]. Lane 127 (w2i=0,b2=0,w2h=w_fc): pre2 == out[n-2]-bfc.
#define ITER(H1R, H2R, H1W, H2W, XV, OUTP, DO_EMIT) { \
    const ulonglong2* hp1 = (const ulonglong2*)(H1R); \
    const ulonglong2* hp2 = (const ulonglong2*)(H2R); \
    float xb = fmaf((XV), k0, b1); \
    ull a0 = 0ull, a1 = 0ull, e0 = 0ull, e1 = 0ull, d0 = 0ull, d1 = 0ull; \
    _Pragma("unroll") \
    for (int k = 0; k < 7; k++) { \
        ulonglong2 v1 = hp1[k]; \
        ulonglong2 v2 = hp2[k]; \
        fma2(a0, w1p[2 * k],     v1.x); \
        fma2(a1, w1p[2 * k + 1], v1.y); \
        fma2(e0, w2i[2 * k],     v1.x); \
        fma2(e1, w2i[2 * k + 1], v1.y); \
        fma2(d0, w2h[2 * k],     v2.x); \
        fma2(d1, w2h[2 * k + 1], v2.y); \
    } \
    { ull v1t = ((const ull*)(H1R))[14], v2t = ((const ull*)(H2R))[14]; \
      fma2(a0, w1p[14], v1t); \
      fma2(e0, w2i[14], v1t); \
      fma2(d0, w2h[14], v2t); } \
    float pre1 = xb + hadd(add2(a0, a1)); \
    float pre2 = b2 + hadd(add2(add2(e0, e1), add2(d0, d1))); \
    if (DO_EMIT) { if (tid == 127) *(OUTP) = pre2 + bfc; } \
    float av = act(pre1, aa, cc); \
    float zv = act(pre2, aa, cc); \
    { \
        float gi = __shfl_sync(0xffffffffu, av, base); \
        float gf = __shfl_sync(0xffffffffu, av, base + 1); \
        float gg = __shfl_sync(0xffffffffu, av, base + 2); \
        c1 = fmaf(gf, c1, gi * gg); \
        if (g == 3) (H1W)[u] = av * tanhs(c1); \
    } \
    { \
        float qi = __shfl_sync(0xffffffffu, zv, base); \
        float qf = __shfl_sync(0xffffffffu, zv, base + 1); \
        float qg = __shfl_sync(0xffffffffu, zv, base + 2); \
        c2 = fmaf(qf, c2, qi * qg); \
        if (g == 3) (H2W)[u] = zv * tanhs(c2); \
    } \
    __syncthreads(); \
}

__global__ void __launch_bounds__(128, 4) lstm_kernel(
    const float* __restrict__ x,
    const float* __restrict__ w_ih1, const float* __restrict__ w_hh1,
    const float* __restrict__ b_ih1, const float* __restrict__ b_hh1,
    const float* __restrict__ w_ih2, const float* __restrict__ w_hh2,
    const float* __restrict__ b_ih2, const float* __restrict__ b_hh2,
    const float* __restrict__ w_fc,  const float* __restrict__ b_fc,
    float* __restrict__ out)
{
    __shared__ __align__(16) float sx[Ts];
    __shared__ __align__(16) float h1A[32], h1B[32];
    __shared__ __align__(16) float h2A[32], h2B[32];

    const int tid  = threadIdx.x;
    const int g    = tid & 3;
    const int u    = tid >> 2;
    const int lane = tid & 31;
    const int base = lane & ~3;
    const int b    = blockIdx.x;

    {   // coalesced x preload
        const float4* xb4 = (const float4*)(x + (size_t)b * Ts);
        float4* sx4 = (float4*)sx;
        #pragma unroll
        for (int i = 0; i < Ts / 4 / 128; i++) sx4[tid + i * 128] = xb4[tid + i * 128];
    }
    if (tid < 32) {
        h1A[tid] = 0.0f; h1B[tid] = 0.0f;
        h2A[tid] = 0.0f; h2B[tid] = 0.0f;
    }

    // Per-lane input scale: sigmoid lanes -log2e, tanh-gate lanes -2log2e.
    const float s = (g == 2) ? -K2E : -L2E;
    const bool  fc_lane = (tid == 127);

    // Register-resident weight rows, PRE-SCALED by s. FC lane (127):
    // w2i = 0, w2h = w_fc (unscaled), b2 = 0 -> its pre2 = w_fc . h2[n-2].
    const int row = g * Hs + ((u < Hs) ? u : Hs - 1);
    ull w1p[15], w2i[15], w2h[15];
    {
        const float* r1  = w_hh1 + row * Hs;
        const float* r2i = w_ih2 + row * Hs;
        const float* r2h = fc_lane ? w_fc : (w_hh2 + row * Hs);
        const float  s2i = fc_lane ? 0.0f : s;
        const float  s2h = fc_lane ? 1.0f : s;
        #pragma unroll
        for (int k = 0; k < 15; k++) {
            w1p[k] = pk(s * r1[2 * k],    s * r1[2 * k + 1]);
            w2i[k] = pk(s2i * r2i[2 * k], s2i * r2i[2 * k + 1]);
            w2h[k] = pk(s2h * r2h[2 * k], s2h * r2h[2 * k + 1]);
        }
    }
    const float k0  = s * w_ih1[row];
    const float b1  = s * (b_ih1[row] + b_hh1[row]);
    const float b2  = fc_lane ? 0.0f : s * (b_ih2[row] + b_hh2[row]);
    const float bfc = b_fc[0];

    const float aa = (g == 2) ? AA_G : 1.0f;
    const float cc = (g == 2) ? CC_G : 0.0f;

    float c1 = 0.0f, c2 = 0.0f;   // SCALED cell states (c' = K2E * c)
    float* __restrict__ outb = out + (size_t)b * Ts;

    __syncthreads();

    // ---- Prologue n = 0: L1 step 0 only (h1[-1]=0) -> h1B ----
    {
        float av = act(fmaf(sx[0], k0, b1), aa, cc);
        float gi = __shfl_sync(0xffffffffu, av, base);
        float gg = __shfl_sync(0xffffffffu, av, base + 2);
        c1 = gi * gg;
        if (g == 3) h1B[u] = av * tanhs(c1);
        __syncthreads();
    }

    // ---- n = 1: read B (h2[-1]=0), write A; no emit ----
    ITER(h1B, h2B, h1A, h2A, sx[1], outb, false);

    // ---- Steady: n = 2..2047, unrolled x4 (two ping-pong pairs) ----
    const float* sxp = sx + 2;
    float* op = outb;   // op[0] = out[n-2] at the first (even) step
    #pragma unroll 1
    for (int k4 = 0; k4 < 511; k4++) {
        ITER(h1A, h2A, h1B, h2B, sxp[0], op,     true);
        ITER(h1B, h2B, h1A, h2A, sxp[1], op + 1, true);
        ITER(h1A, h2A, h1B, h2B, sxp[2], op + 2, true);
        ITER(h1B, h2B, h1A, h2A, sxp[3], op + 3, true);
        sxp += 4;
        op  += 4;
    }
    ITER(h1A, h2A, h1B, h2B, sxp[0], op,     true);
    ITER(h1B, h2B, h1A, h2A, sxp[1], op + 1, true);
    // After steady: h1A = h1[2047], h2A = h2[2046]; emitted out[0..2045].

    // ---- Epilogue: L2-only step 2047; lane 127 emits out[2046] ----
    {
        const ulonglong2* hp1 = (const ulonglong2*)h1A;
        const ulonglong2* hp2 = (const ulonglong2*)h2A;
        ull e0 = 0ull, e1 = 0ull, d0 = 0ull, d1 = 0ull;
        #pragma unroll
        for (int k = 0; k < 7; k++) {
            ulonglong2 v1 = hp1[k];
            ulonglong2 v2 = hp2[k];
            fma2(e0, w2i[2 * k],     v1.x);
            fma2(e1, w2i[2 * k + 1], v1.y);
            fma2(d0, w2h[2 * k],     v2.x);
            fma2(d1, w2h[2 * k + 1], v2.y);
        }
        fma2(e0, w2i[14], ((const ull*)h1A)[14]);
        fma2(d0, w2h[14], ((const ull*)h2A)[14]);
        float pre2 = b2 + hadd(add2(add2(e0, e1), add2(d0, d1)));
        if (tid == 127) outb[Ts - 2] = pre2 + bfc;
        float zv = act(pre2, aa, cc);
        float qi = __shfl_sync(0xffffffffu, zv, base);
        float qf = __shfl_sync(0xffffffffu, zv, base + 1);
        float qg = __shfl_sync(0xffffffffu, zv, base + 2);
        c2 = fmaf(qf, c2, qi * qg);
        if (g == 3) h2B[u] = zv * tanhs(c2);
        __syncthreads();
    }
    // ---- Final: out[2047] = w_fc . h2[2047] (lane 127 mini-dot) ----
    if (tid == 127) {
        const ulonglong2* hp2 = (const ulonglong2*)h2B;
        ull d0 = 0ull, d1 = 0ull;
        #pragma unroll
        for (int k = 0; k < 7; k++) {
            ulonglong2 v2 = hp2[k];
            fma2(d0, w2h[2 * k],     v2.x);
            fma2(d1, w2h[2 * k + 1], v2.y);
        }
        fma2(d0, w2h[14], ((const ull*)h2B)[14]);
        outb[Ts - 1] = hadd(add2(d0, d1)) + bfc;
    }
}

extern "C" void kernel_launch(void* const* d_in, const int* in_sizes, int n_in,
                              void* d_out, int out_size) {
    (void)in_sizes; (void)n_in; (void)out_size;
    lstm_kernel<<<Bs, 128>>>(
        (const float*)d_in[0],
        (const float*)d_in[1], (const float*)d_in[2],
        (const float*)d_in[3], (const float*)d_in[4],
        (const float*)d_in[5], (const float*)d_in[6],
        (const float*)d_in[7], (const float*)d_in[8],
        (const float*)d_in[9], (const float*)d_in[10],
        (float*)d_out);
}

// round 12
// speedup vs baseline: 1.9088x; 1.3310x over previous
#include <cuda_runtime.h>

// 2-layer LSTM (H=30, IN=1) + linear head, B=512, T=2048.
// Skeleton (R11, 1085us): block = 1 element, 128 thr = 4 warps, QUAD layout
// (g = tid&3: 0=i,1=f,2=g,3=o; u = tid>>2; units 30,31 pad). Weight rows
// register-resident f32x2. Iter n: L1 step n + L2 step n-1 fused, ONE
// __syncthreads/iter, ping-pong buffers, x4-unrolled steady loop. FC head
// folded into lane 127 (w2i=0, b2=0, w2h=w_fc -> pre2 == out[n-2]-bfc).
// This round: ALL activations via hardware tanh.approx.f32 (1 MUFU op):
//   sigmoid(x) = 0.5*tanh(x/2)+0.5  -> weights pre-scaled by 0.5
//   g-gate / cell tanh = tanh.approx directly (cell state back to natural
//   scale; the ex2/rcp forms and scaled-c' machinery are deleted).
// MUFU instrs per lane-iter: 8 -> 4.

#define Hs 30
#define Ts 2048
#define Bs 512

typedef unsigned long long ull;

__device__ __forceinline__ ull pk(float lo, float hi) {
    ull r; asm("mov.b64 %0, {%1, %2};" : "=l"(r) : "f"(lo), "f"(hi)); return r;
}
__device__ __forceinline__ void fma2(ull& d, ull a, ull b) {
    asm("fma.rn.f32x2 %0, %1, %2, %3;" : "=l"(d) : "l"(a), "l"(b), "l"(d));
}
__device__ __forceinline__ ull add2(ull a, ull b) {
    ull r; asm("add.rn.f32x2 %0, %1, %2;" : "=l"(r) : "l"(a), "l"(b)); return r;
}
__device__ __forceinline__ float hadd(ull a) {
    float lo, hi; asm("mov.b64 {%0, %1}, %2;" : "=f"(lo), "=f"(hi) : "l"(a)); return lo + hi;
}
__device__ __forceinline__ float tanha(float x) {
    float y; asm("tanh.approx.f32 %0, %1;" : "=f"(y) : "f"(x)); return y;
}

// act on PRE-SCALED input p (sigmoid lanes: p = 0.5*pre; g lane: p = pre):
//   sigmoid: 0.5*tanh(p) + 0.5    g-gate: tanh(p)
__device__ __forceinline__ float act(float p, float aa, float cc) {
    return fmaf(aa, tanha(p), cc);
}

// One fused iteration. Reads H1R=h1[n-1], H2R=h2[n-2]; writes H1W=h1[n],
// H2W=h2[n-1]. Lane 127 (w2i=0,b2=0,w2h=w_fc): pre2 == out[n-2]-bfc.
#define ITER(H1R, H2R, H1W, H2W, XV, OUTP, DO_EMIT) { \
    const ulonglong2* hp1 = (const ulonglong2*)(H1R); \
    const ulonglong2* hp2 = (const ulonglong2*)(H2R); \
    float xb = fmaf((XV), k0, b1); \
    ull a0 = 0ull, a1 = 0ull, e0 = 0ull, e1 = 0ull, d0 = 0ull, d1 = 0ull; \
    _Pragma("unroll") \
    for (int k = 0; k < 7; k++) { \
        ulonglong2 v1 = hp1[k]; \
        ulonglong2 v2 = hp2[k]; \
        fma2(a0, w1p[2 * k],     v1.x); \
        fma2(a1, w1p[2 * k + 1], v1.y); \
        fma2(e0, w2i[2 * k],     v1.x); \
        fma2(e1, w2i[2 * k + 1], v1.y); \
        fma2(d0, w2h[2 * k],     v2.x); \
        fma2(d1, w2h[2 * k + 1], v2.y); \
    } \
    { ull v1t = ((const ull*)(H1R))[14], v2t = ((const ull*)(H2R))[14]; \
      fma2(a0, w1p[14], v1t); \
      fma2(e0, w2i[14], v1t); \
      fma2(d0, w2h[14], v2t); } \
    float pre1 = xb + hadd(add2(a0, a1)); \
    float pre2 = b2 + hadd(add2(add2(e0, e1), add2(d0, d1))); \
    if (DO_EMIT) { if (tid == 127) *(OUTP) = pre2 + bfc; } \
    float av = act(pre1, aa, cc); \
    float zv = act(pre2, aa, cc); \
    { \
        float gi = __shfl_sync(0xffffffffu, av, base); \
        float gf = __shfl_sync(0xffffffffu, av, base + 1); \
        float gg = __shfl_sync(0xffffffffu, av, base + 2); \
        c1 = fmaf(gf, c1, gi * gg); \
        if (g == 3) (H1W)[u] = av * tanha(c1); \
    } \
    { \
        float qi = __shfl_sync(0xffffffffu, zv, base); \
        float qf = __shfl_sync(0xffffffffu, zv, base + 1); \
        float qg = __shfl_sync(0xffffffffu, zv, base + 2); \
        c2 = fmaf(qf, c2, qi * qg); \
        if (g == 3) (H2W)[u] = zv * tanha(c2); \
    } \
    __syncthreads(); \
}

__global__ void __launch_bounds__(128, 4) lstm_kernel(
    const float* __restrict__ x,
    const float* __restrict__ w_ih1, const float* __restrict__ w_hh1,
    const float* __restrict__ b_ih1, const float* __restrict__ b_hh1,
    const float* __restrict__ w_ih2, const float* __restrict__ w_hh2,
    const float* __restrict__ b_ih2, const float* __restrict__ b_hh2,
    const float* __restrict__ w_fc,  const float* __restrict__ b_fc,
    float* __restrict__ out)
{
    __shared__ __align__(16) float sx[Ts];
    __shared__ __align__(16) float h1A[32], h1B[32];
    __shared__ __align__(16) float h2A[32], h2B[32];

    const int tid  = threadIdx.x;
    const int g    = tid & 3;
    const int u    = tid >> 2;
    const int lane = tid & 31;
    const int base = lane & ~3;
    const int b    = blockIdx.x;

    {   // coalesced x preload
        const float4* xb4 = (const float4*)(x + (size_t)b * Ts);
        float4* sx4 = (float4*)sx;
        #pragma unroll
        for (int i = 0; i < Ts / 4 / 128; i++) sx4[tid + i * 128] = xb4[tid + i * 128];
    }
    if (tid < 32) {
        h1A[tid] = 0.0f; h1B[tid] = 0.0f;
        h2A[tid] = 0.0f; h2B[tid] = 0.0f;
    }

    // Per-lane input scale: sigmoid lanes 0.5 (tanh(x/2) form), g lane 1.0.
    const float s = (g == 2) ? 1.0f : 0.5f;
    const bool  fc_lane = (tid == 127);

    // Register-resident weight rows, PRE-SCALED by s. FC lane (127):
    // w2i = 0, w2h = w_fc (unscaled), b2 = 0 -> its pre2 = w_fc . h2[n-2].
    const int row = g * Hs + ((u < Hs) ? u : Hs - 1);
    ull w1p[15], w2i[15], w2h[15];
    {
        const float* r1  = w_hh1 + row * Hs;
        const float* r2i = w_ih2 + row * Hs;
        const float* r2h = fc_lane ? w_fc : (w_hh2 + row * Hs);
        const float  s2i = fc_lane ? 0.0f : s;
        const float  s2h = fc_lane ? 1.0f : s;
        #pragma unroll
        for (int k = 0; k < 15; k++) {
            w1p[k] = pk(s * r1[2 * k],    s * r1[2 * k + 1]);
            w2i[k] = pk(s2i * r2i[2 * k], s2i * r2i[2 * k + 1]);
            w2h[k] = pk(s2h * r2h[2 * k], s2h * r2h[2 * k + 1]);
        }
    }
    const float k0  = s * w_ih1[row];
    const float b1  = s * (b_ih1[row] + b_hh1[row]);
    const float b2  = fc_lane ? 0.0f : s * (b_ih2[row] + b_hh2[row]);
    const float bfc = b_fc[0];

    // Activation output constants: sigmoid lanes 0.5*t+0.5; g lane t.
    const float aa = (g == 2) ? 1.0f : 0.5f;
    const float cc = (g == 2) ? 0.0f : 0.5f;

    float c1 = 0.0f, c2 = 0.0f;
    float* __restrict__ outb = out + (size_t)b * Ts;

    __syncthreads();

    // ---- Prologue n = 0: L1 step 0 only (h1[-1]=0) -> h1B ----
    {
        float av = act(fmaf(sx[0], k0, b1), aa, cc);
        float gi = __shfl_sync(0xffffffffu, av, base);
        float gg = __shfl_sync(0xffffffffu, av, base + 2);
        c1 = gi * gg;
        if (g == 3) h1B[u] = av * tanha(c1);
        __syncthreads();
    }

    // ---- n = 1: read B (h2[-1]=0), write A; no emit ----
    ITER(h1B, h2B, h1A, h2A, sx[1], outb, false);

    // ---- Steady: n = 2..2047, unrolled x4 (two ping-pong pairs) ----
    const float* sxp = sx + 2;
    float* op = outb;   // op[0] = out[n-2] at the first (even) step
    #pragma unroll 1
    for (int k4 = 0; k4 < 511; k4++) {
        ITER(h1A, h2A, h1B, h2B, sxp[0], op,     true);
        ITER(h1B, h2B, h1A, h2A, sxp[1], op + 1, true);
        ITER(h1A, h2A, h1B, h2B, sxp[2], op + 2, true);
        ITER(h1B, h2B, h1A, h2A, sxp[3], op + 3, true);
        sxp += 4;
        op  += 4;
    }
    ITER(h1A, h2A, h1B, h2B, sxp[0], op,     true);
    ITER(h1B, h2B, h1A, h2A, sxp[1], op + 1, true);
    // After steady: h1A = h1[2047], h2A = h2[2046]; emitted out[0..2045].

    // ---- Epilogue: L2-only step 2047; lane 127 emits out[2046] ----
    {
        const ulonglong2* hp1 = (const ulonglong2*)h1A;
        const ulonglong2* hp2 = (const ulonglong2*)h2A;
        ull e0 = 0ull, e1 = 0ull, d0 = 0ull, d1 = 0ull;
        #pragma unroll
        for (int k = 0; k < 7; k++) {
            ulonglong2 v1 = hp1[k];
            ulonglong2 v2 = hp2[k];
            fma2(e0, w2i[2 * k],     v1.x);
            fma2(e1, w2i[2 * k + 1], v1.y);
            fma2(d0, w2h[2 * k],     v2.x);
            fma2(d1, w2h[2 * k + 1], v2.y);
        }
        fma2(e0, w2i[14], ((const ull*)h1A)[14]);
        fma2(d0, w2h[14], ((const ull*)h2A)[14]);
        float pre2 = b2 + hadd(add2(add2(e0, e1), add2(d0, d1)));
        if (tid == 127) outb[Ts - 2] = pre2 + bfc;
        float zv = act(pre2, aa, cc);
        float qi = __shfl_sync(0xffffffffu, zv, base);
        float qf = __shfl_sync(0xffffffffu, zv, base + 1);
        float qg = __shfl_sync(0xffffffffu, zv, base + 2);
        c2 = fmaf(qf, c2, qi * qg);
        if (g == 3) h2B[u] = zv * tanha(c2);
        __syncthreads();
    }
    // ---- Final: out[2047] = w_fc . h2[2047] (lane 127 mini-dot) ----
    if (tid == 127) {
        const ulonglong2* hp2 = (const ulonglong2*)h2B;
        ull d0 = 0ull, d1 = 0ull;
        #pragma unroll
        for (int k = 0; k < 7; k++) {
            ulonglong2 v2 = hp2[k];
            fma2(d0, w2h[2 * k],     v2.x);
            fma2(d1, w2h[2 * k + 1], v2.y);
        }
        fma2(d0, w2h[14], ((const ull*)h2B)[14]);
        outb[Ts - 1] = hadd(add2(d0, d1)) + bfc;
    }
}

extern "C" void kernel_launch(void* const* d_in, const int* in_sizes, int n_in,
                              void* d_out, int out_size) {
    (void)in_sizes; (void)n_in; (void)out_size;
    lstm_kernel<<<Bs, 128>>>(
        (const float*)d_in[0],
        (const float*)d_in[1], (const float*)d_in[2],
        (const float*)d_in[3], (const float*)d_in[4],
        (const float*)d_in[5], (const float*)d_in[6],
        (const float*)d_in[7], (const float*)d_in[8],
        (const float*)d_in[9], (const float*)d_in[10],
        (float*)d_out);
}